// round 4
// baseline (speedup 1.0000x reference)
#include <cuda_runtime.h>
#include <cuda_bf16.h>
#include <mma.h>

using namespace nvcuda;

#define NROWS 8192
#define DIM   1024
#define INV_T 10.0f

// ---------------- scratch (device globals; no allocation) ----------------
__device__ __nv_bfloat16 g_imn[NROWS * DIM];   // 16 MB
__device__ __nv_bfloat16 g_capn[NROWS * DIM];  // 16 MB
__device__ float g_rowsum[NROWS];
__device__ float g_colsum[NROWS];
__device__ float g_diag[NROWS];

// ---------------- 1) normalize rows, write bf16 ----------------
__global__ void normalize_kernel(const float* __restrict__ im,
                                 const float* __restrict__ cap) {
    int row = blockIdx.x;
    const float* src = (blockIdx.y == 0) ? im : cap;
    __nv_bfloat16* dst = (blockIdx.y == 0) ? g_imn : g_capn;

    const float4* src4 = reinterpret_cast<const float4*>(src + (size_t)row * DIM);
    float4 v = src4[threadIdx.x];           // 256 threads * 4 = 1024
    float ss = v.x * v.x + v.y * v.y + v.z * v.z + v.w * v.w;

    #pragma unroll
    for (int o = 16; o; o >>= 1) ss += __shfl_xor_sync(0xffffffffu, ss, o);

    __shared__ float wss[8];
    if ((threadIdx.x & 31) == 0) wss[threadIdx.x >> 5] = ss;
    __syncthreads();
    float total = 0.f;
    #pragma unroll
    for (int i = 0; i < 8; i++) total += wss[i];

    float inv = rsqrtf(total);
    __nv_bfloat162* d2 = reinterpret_cast<__nv_bfloat162*>(dst + (size_t)row * DIM);
    d2[threadIdx.x * 2 + 0] = __floats2bfloat162_rn(v.x * inv, v.y * inv);
    d2[threadIdx.x * 2 + 1] = __floats2bfloat162_rn(v.z * inv, v.w * inv);
}

// ---------------- 2) zero accumulators ----------------
__global__ void zero_kernel() {
    int i = blockIdx.x * blockDim.x + threadIdx.x;
    if (i < NROWS) {
        g_rowsum[i] = 0.f;
        g_colsum[i] = 0.f;
        g_diag[i]   = 0.f;
    }
}

// ---------------- 3) fused GEMM + exp + row/col reduction ----------------
// Block tile 128x128, 8 warps (2x4), warp tile 64x32 = 4x2 wmma 16x16x16 frags.
#define BM 128
#define BN 128
#define BK 16
#define LDS_AB 24   // bf16 smem leading dim (48B rows, mult of 16B)
#define LDS_FB 20   // f32 fragment-buffer leading dim (80B, mult of 16B)

__global__ __launch_bounds__(256) void gemm_kernel() {
    __shared__ __align__(16) __nv_bfloat16 As[BM * LDS_AB];
    __shared__ __align__(16) __nv_bfloat16 Bs[BN * LDS_AB];
    __shared__ __align__(16) float fragbuf[8][16 * LDS_FB];
    __shared__ float rowsum_s[BM];
    __shared__ float colsum_s[BN];

    const int tid  = threadIdx.x;
    const int warp = tid >> 5;
    const int lane = tid & 31;
    const int warpM = warp >> 2;   // 0..1  -> 64-row slab
    const int warpN = warp & 3;    // 0..3  -> 32-col slab
    const int rowBase = blockIdx.y * BM;
    const int colBase = blockIdx.x * BN;

    if (tid < BM) rowsum_s[tid] = 0.f;
    else          colsum_s[tid - BM] = 0.f;

    wmma::fragment<wmma::accumulator, 16, 16, 16, float> acc[4][2];
    #pragma unroll
    for (int i = 0; i < 4; i++)
        #pragma unroll
        for (int j = 0; j < 2; j++)
            wmma::fill_fragment(acc[i][j], 0.0f);

    const int ldRow = tid >> 1;          // 0..127
    const int ldK   = (tid & 1) * 8;     // 0 or 8

    const size_t aBase = (size_t)(rowBase + ldRow) * DIM + ldK;
    const size_t bBase = (size_t)(colBase + ldRow) * DIM + ldK;

    for (int k0 = 0; k0 < DIM; k0 += BK) {
        uint4 a = *reinterpret_cast<const uint4*>(&g_imn[aBase + k0]);
        uint4 b = *reinterpret_cast<const uint4*>(&g_capn[bBase + k0]);
        __syncthreads();  // previous iteration's frag loads done
        *reinterpret_cast<uint4*>(&As[ldRow * LDS_AB + ldK]) = a;
        *reinterpret_cast<uint4*>(&Bs[ldRow * LDS_AB + ldK]) = b;
        __syncthreads();

        wmma::fragment<wmma::matrix_a, 16, 16, 16, __nv_bfloat16, wmma::row_major> af[4];
        wmma::fragment<wmma::matrix_b, 16, 16, 16, __nv_bfloat16, wmma::col_major> bf[2];
        #pragma unroll
        for (int i = 0; i < 4; i++)
            wmma::load_matrix_sync(af[i], &As[(warpM * 64 + i * 16) * LDS_AB], LDS_AB);
        #pragma unroll
        for (int j = 0; j < 2; j++)
            wmma::load_matrix_sync(bf[j], &Bs[(warpN * 32 + j * 16) * LDS_AB], LDS_AB);

        #pragma unroll
        for (int i = 0; i < 4; i++)
            #pragma unroll
            for (int j = 0; j < 2; j++)
                wmma::mma_sync(acc[i][j], af[i], bf[j], acc[i][j]);
    }

    // ---- epilogue: per-fragment exp + row/col partial sums ----
    float* fb = fragbuf[warp];
    #pragma unroll
    for (int i = 0; i < 4; i++) {
        #pragma unroll
        for (int j = 0; j < 2; j++) {
            wmma::store_matrix_sync(fb, acc[i][j], LDS_FB, wmma::mem_row_major);
            __syncwarp();

            const int giBase = rowBase + warpM * 64 + i * 16;
            const int gjBase = colBase + warpN * 32 + j * 16;

            // row pass: lane -> (r = lane&15, half = lane>>4 selects 8 cols)
            {
                int r = lane & 15;
                int half = lane >> 4;
                int gi = giBase + r;
                float s = 0.f;
                #pragma unroll
                for (int cc = 0; cc < 8; cc++) {
                    int c = half * 8 + cc;
                    float v = fb[r * LDS_FB + c] * INV_T;
                    if (gi == gjBase + c) g_diag[gi] = v;   // diagonal logit
                    float e = __expf(v);
                    fb[r * LDS_FB + c] = e;                 // reuse for col pass
                    s += e;
                }
                s += __shfl_down_sync(0xffffffffu, s, 16);
                if (half == 0) atomicAdd(&rowsum_s[warpM * 64 + i * 16 + r], s);
            }
            __syncwarp();

            // col pass: lane -> (c = lane&15, half selects 8 rows)
            {
                int c = lane & 15;
                int half = lane >> 4;
                float s = 0.f;
                #pragma unroll
                for (int rr = 0; rr < 8; rr++)
                    s += fb[(half * 8 + rr) * LDS_FB + c];
                s += __shfl_down_sync(0xffffffffu, s, 16);
                if (half == 0) atomicAdd(&colsum_s[warpN * 32 + j * 16 + c], s);
            }
            __syncwarp();
        }
    }

    __syncthreads();
    if (tid < BM) atomicAdd(&g_rowsum[rowBase + tid], rowsum_s[tid]);
    else          atomicAdd(&g_colsum[colBase + tid - BM], colsum_s[tid - BM]);
}

// ---------------- 4) finalize ----------------
__global__ void finalize_kernel(float* __restrict__ out) {
    int tid = threadIdx.x;
    float a = 0.f, d = 0.f;
    for (int i = tid; i < NROWS; i += 256) {
        a += logf(g_rowsum[i]) + logf(g_colsum[i]);
        d += g_diag[i];
    }
    #pragma unroll
    for (int o = 16; o; o >>= 1) {
        a += __shfl_xor_sync(0xffffffffu, a, o);
        d += __shfl_xor_sync(0xffffffffu, d, o);
    }
    __shared__ float sa[8], sd[8];
    if ((tid & 31) == 0) { sa[tid >> 5] = a; sd[tid >> 5] = d; }
    __syncthreads();
    if (tid == 0) {
        float ta = 0.f, td = 0.f;
        #pragma unroll
        for (int i = 0; i < 8; i++) { ta += sa[i]; td += sd[i]; }
        out[0] = 0.5f * ta / (float)NROWS - td / (float)NROWS;
    }
}

// ---------------- launch ----------------
extern "C" void kernel_launch(void* const* d_in, const int* in_sizes, int n_in,
                              void* d_out, int out_size) {
    const float* im  = (const float*)d_in[0];
    const float* cap = (const float*)d_in[1];
    float* out = (float*)d_out;

    normalize_kernel<<<dim3(NROWS, 2), 256>>>(im, cap);
    zero_kernel<<<(NROWS + 255) / 256, 256>>>();
    gemm_kernel<<<dim3(NROWS / BN, NROWS / BM), 256>>>();
    finalize_kernel<<<1, 256>>>(out);
}

// round 7
// speedup vs baseline: 2.3203x; 2.3203x over previous
#include <cuda_runtime.h>
#include <cuda_bf16.h>
#include <cstdint>

#define NROWS 8192
#define DIM   1024
#define SCALE_T 14.4269504088896341f   // (1/T)*log2(e)
#define LN2F 0.69314718055994531f

// ---------------- scratch ----------------
__device__ __nv_bfloat16 g_imn[(size_t)NROWS * DIM];   // normalized * SCALE_T
__device__ __nv_bfloat16 g_capn[(size_t)NROWS * DIM];  // normalized
__device__ float g_rowsum[NROWS];
__device__ float g_colsum[NROWS];
__device__ float g_diag[NROWS];                        // t_ii (exp2-domain logits)

// ---------------- helpers ----------------
__device__ __forceinline__ uint32_t smem_u32(const void* p) {
    uint32_t a;
    asm("{ .reg .u64 t; cvta.to.shared.u64 t, %1; cvt.u32.u64 %0, t; }" : "=r"(a) : "l"(p));
    return a;
}
__device__ __forceinline__ uint64_t gmem_u64(const void* p) {
    uint64_t a;
    asm("cvta.to.global.u64 %0, %1;" : "=l"(a) : "l"(p));
    return a;
}
#define SW128(o) ((o) ^ (((o) >> 3) & 0x70))

// ---------------- 1) normalize ----------------
__global__ void normalize_kernel(const float* __restrict__ im,
                                 const float* __restrict__ cap) {
    int row = blockIdx.x;
    const float* src = (blockIdx.y == 0) ? im : cap;
    __nv_bfloat16* dst = (blockIdx.y == 0) ? g_imn : g_capn;
    float cscale = (blockIdx.y == 0) ? SCALE_T : 1.0f;

    const float4* src4 = reinterpret_cast<const float4*>(src + (size_t)row * DIM);
    float4 v = src4[threadIdx.x];
    float ss = v.x * v.x + v.y * v.y + v.z * v.z + v.w * v.w;
    #pragma unroll
    for (int o = 16; o; o >>= 1) ss += __shfl_xor_sync(0xffffffffu, ss, o);
    __shared__ float wss[8];
    if ((threadIdx.x & 31) == 0) wss[threadIdx.x >> 5] = ss;
    __syncthreads();
    float total = 0.f;
    #pragma unroll
    for (int i = 0; i < 8; i++) total += wss[i];

    float inv = rsqrtf(total) * cscale;
    __nv_bfloat162* d2 = reinterpret_cast<__nv_bfloat162*>(dst + (size_t)row * DIM);
    d2[threadIdx.x * 2 + 0] = __floats2bfloat162_rn(v.x * inv, v.y * inv);
    d2[threadIdx.x * 2 + 1] = __floats2bfloat162_rn(v.z * inv, v.w * inv);
}

// ---------------- 2) zero ----------------
__global__ void zero_kernel() {
    int i = blockIdx.x * blockDim.x + threadIdx.x;
    if (i < NROWS) { g_rowsum[i] = 0.f; g_colsum[i] = 0.f; }
}

// ---------------- 3) diag: t_ii = dot(imn_scaled[i], capn[i]) ----------------
__global__ void diag_kernel() {
    int wid = threadIdx.x >> 5, lane = threadIdx.x & 31;
    int row = blockIdx.x * 8 + wid;
    const uint4* A = reinterpret_cast<const uint4*>(g_imn + (size_t)row * DIM);
    const uint4* B = reinterpret_cast<const uint4*>(g_capn + (size_t)row * DIM);
    float acc = 0.f;
    #pragma unroll
    for (int q = 0; q < 4; q++) {
        uint4 a = A[lane + 32 * q], b = B[lane + 32 * q];
        const __nv_bfloat162* pa = reinterpret_cast<const __nv_bfloat162*>(&a);
        const __nv_bfloat162* pb = reinterpret_cast<const __nv_bfloat162*>(&b);
        #pragma unroll
        for (int j = 0; j < 4; j++) {
            float2 fa = __bfloat1622float2(pa[j]);
            float2 fb = __bfloat1622float2(pb[j]);
            acc += fa.x * fb.x + fa.y * fb.y;
        }
    }
    #pragma unroll
    for (int o = 16; o; o >>= 1) acc += __shfl_xor_sync(0xffffffffu, acc, o);
    if (lane == 0) g_diag[row] = acc;
}

// ---------------- 4) mma.sync GEMM + exp2 + in-register row/col reduce ----------------
// CTA tile 128x128, BK=64, 3-stage cp.async pipeline. 8 warps = 2(M) x 4(N).
// Warp tile 64x32 = 4 m-frags (m16) x 4 n-frags (n8).
#define BM 128
#define BN 128
#define BK 64
#define STAGE_BYTES 32768                 // A 16KB + B 16KB
#define DYN_BYTES (3 * STAGE_BYTES + 1024)

extern __shared__ char dynsmem[];

__device__ __forceinline__ void issue_tile(uint32_t sStage, uint64_t gA, uint64_t gB,
                                           int c, int tid) {
    // tile rows: chunk>>3 (8x16B chunks per 128B row of 64 bf16)
    const uint32_t k0b = (uint32_t)c * (BK * 2);  // byte offset along K
    #pragma unroll
    for (int q = 0; q < 4; q++) {
        int chunk = tid + q * 256;
        int row = chunk >> 3, kc = chunk & 7;
        uint32_t soff = SW128(row * 128 + kc * 16);
        uint64_t goff = (uint64_t)row * (DIM * 2) + k0b + kc * 16;
        asm volatile("cp.async.cg.shared.global [%0], [%1], 16;"
                     :: "r"(sStage + soff), "l"(gA + goff) : "memory");
        asm volatile("cp.async.cg.shared.global [%0], [%1], 16;"
                     :: "r"(sStage + 16384 + soff), "l"(gB + goff) : "memory");
    }
}

__global__ void __launch_bounds__(256, 2) gemm_kernel() {
    const int tid = threadIdx.x, wid = tid >> 5, lane = tid & 31;
    const int warpM = wid >> 2;           // 0..1 -> 64-row slab
    const int warpN = wid & 3;            // 0..3 -> 32-col slab
    const int rowBase = blockIdx.y * BM;
    const int colBase = blockIdx.x * BN;

    __shared__ float rowsum_s[BM];
    __shared__ float colsum_s[BN];
    if (tid < BM) { rowsum_s[tid] = 0.f; colsum_s[tid] = 0.f; }

    uint32_t raw = smem_u32(dynsmem);
    uint32_t sbase = (raw + 1023u) & ~1023u;

    const uint64_t gA = gmem_u64(&g_imn[(size_t)rowBase * DIM]);
    const uint64_t gB = gmem_u64(&g_capn[(size_t)colBase * DIM]);

    // prologue: stages 0,1
    issue_tile(sbase + 0 * STAGE_BYTES, gA, gB, 0, tid);
    asm volatile("cp.async.commit_group;" ::: "memory");
    issue_tile(sbase + 1 * STAGE_BYTES, gA, gB, 1, tid);
    asm volatile("cp.async.commit_group;" ::: "memory");

    float acc[4][4][4];
    #pragma unroll
    for (int i = 0; i < 4; i++)
        #pragma unroll
        for (int j = 0; j < 4; j++)
            #pragma unroll
            for (int r = 0; r < 4; r++) acc[i][j][r] = 0.f;

    // ldmatrix lane geometry (precomputed)
    const int laneRow = lane & 15;
    const uint32_t aXor = (uint32_t)((laneRow & 7) << 4);
    const uint32_t aHi  = (uint32_t)((lane >> 4) * 16);
    const int rowB0 = ((lane >> 4) & 1) * 8 + (lane & 7);   // within 16-row block
    const uint32_t bXor = (uint32_t)((lane & 7) << 4);
    const uint32_t bHi  = (uint32_t)(((lane >> 3) & 1) * 16);

    for (int c = 0; c < 16; c++) {
        asm volatile("cp.async.wait_group 1;" ::: "memory");
        __syncthreads();
        if (c + 2 < 16)
            issue_tile(sbase + ((c + 2) % 3) * STAGE_BYTES, gA, gB, c + 2, tid);
        asm volatile("cp.async.commit_group;" ::: "memory");

        const uint32_t sA = sbase + (c % 3) * STAGE_BYTES;
        const uint32_t sB = sA + 16384;

        #pragma unroll
        for (int kk = 0; kk < 4; kk++) {
            uint32_t a[4][4], b[2][4];
            #pragma unroll
            for (int i = 0; i < 4; i++) {
                uint32_t addr = sA + (uint32_t)(warpM * 64 + i * 16 + laneRow) * 128
                              + (((uint32_t)kk * 32 + aHi) ^ aXor);
                asm volatile("ldmatrix.sync.aligned.m8n8.x4.shared.b16 {%0,%1,%2,%3}, [%4];"
                             : "=r"(a[i][0]), "=r"(a[i][1]), "=r"(a[i][2]), "=r"(a[i][3])
                             : "r"(addr));
            }
            #pragma unroll
            for (int jb = 0; jb < 2; jb++) {
                uint32_t addr = sB + (uint32_t)(warpN * 32 + jb * 16 + rowB0) * 128
                              + (((uint32_t)kk * 32 + bHi) ^ bXor);
                asm volatile("ldmatrix.sync.aligned.m8n8.x4.shared.b16 {%0,%1,%2,%3}, [%4];"
                             : "=r"(b[jb][0]), "=r"(b[jb][1]), "=r"(b[jb][2]), "=r"(b[jb][3])
                             : "r"(addr));
            }
            #pragma unroll
            for (int i = 0; i < 4; i++) {
                #pragma unroll
                for (int j = 0; j < 4; j++) {
                    uint32_t b0 = b[j >> 1][(j & 1) * 2];
                    uint32_t b1 = b[j >> 1][(j & 1) * 2 + 1];
                    asm volatile(
                        "mma.sync.aligned.m16n8k16.row.col.f32.bf16.bf16.f32 "
                        "{%0,%1,%2,%3}, {%4,%5,%6,%7}, {%8,%9}, {%0,%1,%2,%3};"
                        : "+f"(acc[i][j][0]), "+f"(acc[i][j][1]),
                          "+f"(acc[i][j][2]), "+f"(acc[i][j][3])
                        : "r"(a[i][0]), "r"(a[i][1]), "r"(a[i][2]), "r"(a[i][3]),
                          "r"(b0), "r"(b1));
                }
            }
        }
    }

    // ---- epilogue: exp2 in place, then register reductions ----
    #pragma unroll
    for (int i = 0; i < 4; i++)
        #pragma unroll
        for (int j = 0; j < 4; j++)
            #pragma unroll
            for (int r = 0; r < 4; r++)
                asm("ex2.approx.f32 %0, %0;" : "+f"(acc[i][j][r]));

    // row sums: thread owns rows (lane>>2) and +8 of each m-frag, cols (lane&3)*2..+1 of each n-frag
    #pragma unroll
    for (int i = 0; i < 4; i++) {
        float r0 = 0.f, r1 = 0.f;
        #pragma unroll
        for (int j = 0; j < 4; j++) {
            r0 += acc[i][j][0] + acc[i][j][1];
            r1 += acc[i][j][2] + acc[i][j][3];
        }
        r0 += __shfl_xor_sync(0xffffffffu, r0, 1);
        r0 += __shfl_xor_sync(0xffffffffu, r0, 2);
        r1 += __shfl_xor_sync(0xffffffffu, r1, 1);
        r1 += __shfl_xor_sync(0xffffffffu, r1, 2);
        if ((lane & 3) == 0) {
            int rbase = warpM * 64 + i * 16 + (lane >> 2);
            atomicAdd(&rowsum_s[rbase], r0);
            atomicAdd(&rowsum_s[rbase + 8], r1);
        }
    }
    // col sums
    #pragma unroll
    for (int j = 0; j < 4; j++) {
        float c0 = 0.f, c1 = 0.f;
        #pragma unroll
        for (int i = 0; i < 4; i++) {
            c0 += acc[i][j][0] + acc[i][j][2];
            c1 += acc[i][j][1] + acc[i][j][3];
        }
        c0 += __shfl_xor_sync(0xffffffffu, c0, 4);
        c0 += __shfl_xor_sync(0xffffffffu, c0, 8);
        c0 += __shfl_xor_sync(0xffffffffu, c0, 16);
        c1 += __shfl_xor_sync(0xffffffffu, c1, 4);
        c1 += __shfl_xor_sync(0xffffffffu, c1, 8);
        c1 += __shfl_xor_sync(0xffffffffu, c1, 16);
        if (lane < 4) {
            int cbase = warpN * 32 + j * 8 + lane * 2;
            atomicAdd(&colsum_s[cbase], c0);
            atomicAdd(&colsum_s[cbase + 1], c1);
        }
    }

    __syncthreads();
    if (tid < BM) {
        atomicAdd(&g_rowsum[rowBase + tid], rowsum_s[tid]);
        atomicAdd(&g_colsum[colBase + tid], colsum_s[tid]);
    }
}

// ---------------- 5) finalize ----------------
__global__ void finalize_kernel(float* __restrict__ out) {
    int tid = threadIdx.x;
    float a = 0.f, d = 0.f;
    for (int i = tid; i < NROWS; i += 256) {
        a += log2f(g_rowsum[i]) + log2f(g_colsum[i]);
        d += g_diag[i];
    }
    #pragma unroll
    for (int o = 16; o; o >>= 1) {
        a += __shfl_xor_sync(0xffffffffu, a, o);
        d += __shfl_xor_sync(0xffffffffu, d, o);
    }
    __shared__ float sa[8], sd[8];
    if ((tid & 31) == 0) { sa[tid >> 5] = a; sd[tid >> 5] = d; }
    __syncthreads();
    if (tid == 0) {
        float ta = 0.f, td = 0.f;
        #pragma unroll
        for (int i = 0; i < 8; i++) { ta += sa[i]; td += sd[i]; }
        out[0] = LN2F * (0.5f * ta / (float)NROWS - td / (float)NROWS);
    }
}

// ---------------- launch ----------------
extern "C" void kernel_launch(void* const* d_in, const int* in_sizes, int n_in,
                              void* d_out, int out_size) {
    const float* im  = (const float*)d_in[0];
    const float* cap = (const float*)d_in[1];
    float* out = (float*)d_out;

    cudaFuncSetAttribute(gemm_kernel, cudaFuncAttributeMaxDynamicSharedMemorySize, DYN_BYTES);

    normalize_kernel<<<dim3(NROWS, 2), 256>>>(im, cap);
    zero_kernel<<<(NROWS + 255) / 256, 256>>>();
    diag_kernel<<<NROWS / 8, 256>>>();
    gemm_kernel<<<dim3(NROWS / BN, NROWS / BM), 256, DYN_BYTES>>>();
    finalize_kernel<<<1, 256>>>(out);
}